// round 5
// baseline (speedup 1.0000x reference)
#include <cuda_runtime.h>
#include <cstdint>

#define NB    5
#define HWPX  65536
#define NP    (NB*HWPX)
#define NCH   256
#define NBUCK 32768         // valid dsc < 0x80000000 -> bucket < 32768
#define NTILE 32            // 32 tiles of 1024 buckets per batch
#define WCAP  4096

// ---- static device scratch (allocation-free) ----
__device__ unsigned int       g_dsc[NP];           // descending-order key of best utility
__device__ unsigned char      g_g8[NP];            // argmax group 0/1/2
__device__ signed char        g_selmap[NP];        // accepted group or -1
__device__ unsigned long long g_hist[NB*NBUCK];    // packed: cost | c1<<20 | c2<<40
__device__ unsigned long long g_tile[NB*NTILE];
__device__ unsigned long long g_window[NB*WCAP];
__device__ int                g_wcount[NB];
__device__ int                g_b0[NB], g_b1[NB];
__device__ float              g_Sbefore[NB];

__device__ __forceinline__ float load_budget(const void* ptr) {
    int iv = *(const int*)ptr;                       // int32 or float32 scalar
    if (iv > 0 && iv < 100000000) return (float)iv;
    return __int_as_float(iv);
}
__device__ __forceinline__ int cost_of(int g) { return (g == 0) ? 4 : (g == 1) ? 2 : 1; }

// ---- per-pixel argmax + packed histogram ----
__global__ void kArgmax(const float* __restrict__ util) {
    int p = blockIdx.x * blockDim.x + threadIdx.x;
    float u0 = util[3*p], u1 = util[3*p+1], u2 = util[3*p+2];
    int g = 0; float bu = u0;
    if (u1 > bu) { bu = u1; g = 1; }   // strict >: first max wins (jnp.argmax)
    if (u2 > bu) { bu = u2; g = 2; }
    bool valid = bu > 0.0f;
    unsigned int x = __float_as_uint(bu);
    unsigned int dsc = ~((x & 0x80000000u) ? ~x : (x | 0x80000000u)); // descending map
    if (!valid) dsc = 0xFFFFFFFFu;
    g_dsc[p] = dsc; g_g8[p] = (unsigned char)g;
    if (valid) {
        unsigned long long inc = (unsigned long long)cost_of(g)
            | ((unsigned long long)(g == 1) << 20)
            | ((unsigned long long)(g == 2) << 40);
        atomicAdd(&g_hist[(p >> 16) * NBUCK + (dsc >> 16)], inc);
    }
}

// ---- per-tile (1024 buckets) packed sums ----
__global__ void kTileSum() {
    __shared__ unsigned long long sh[256];
    int t = threadIdx.x;
    const unsigned long long* src = g_hist + (size_t)blockIdx.x * 1024;
    sh[t] = src[t] + src[t+256] + src[t+512] + src[t+768];
    __syncthreads();
    for (int off = 128; off > 0; off >>= 1) {
        if (t < off) sh[t] += sh[t + off];
        __syncthreads();
    }
    if (t == 0) g_tile[blockIdx.x] = sh[0];
}

// ---- one block (1024 thr) per batch: crossing bucket b0 + window end b1 ----
__global__ void kFindWindow(const void* __restrict__ budget_p) {
    __shared__ unsigned s_tile[NTILE];
    __shared__ unsigned s_wsum[32];
    __shared__ int s_ctile, s_b0;
    __shared__ unsigned s_cumbase, s_Sb;

    int b = blockIdx.x, t = threadIdx.x;
    int wid = t >> 5, lane = t & 31;
    float budget = load_budget(budget_p) / (float)NB;
    const unsigned long long* hist = g_hist + (size_t)b * NBUCK;

    if (t < NTILE) s_tile[t] = (unsigned)(g_tile[b*NTILE + t] & 0xFFFFFu);
    if (t == 0) { s_ctile = -1; s_cumbase = 0; s_b0 = NBUCK; s_Sb = 0; }
    __syncthreads();

    if (t == 0) {   // tile-level crossing
        unsigned cum = 0;
        for (int q = 0; q < NTILE; q++) {
            unsigned c = s_tile[q];
            if ((float)(cum + c) > budget) { s_ctile = q; s_cumbase = cum; break; }
            cum += c;
        }
    }
    __syncthreads();
    int ctile = s_ctile;

    if (ctile >= 0) {   // in-tile block scan over 1024 buckets
        unsigned c = (unsigned)(hist[ctile*1024 + t] & 0xFFFFFu);
        unsigned inc = c;
        #pragma unroll
        for (int off = 1; off < 32; off <<= 1) {
            unsigned v = __shfl_up_sync(0xffffffffu, inc, off);
            if (lane >= off) inc += v;
        }
        if (lane == 31) s_wsum[wid] = inc;
        __syncthreads();
        if (wid == 0) {
            unsigned w = s_wsum[lane];
            #pragma unroll
            for (int off = 1; off < 32; off <<= 1) {
                unsigned v = __shfl_up_sync(0xffffffffu, w, off);
                if (lane >= off) w += v;
            }
            s_wsum[lane] = w;
        }
        __syncthreads();
        unsigned woff = (wid > 0) ? s_wsum[wid-1] : 0u;
        unsigned inclT = s_cumbase + woff + inc;
        unsigned excl  = inclT - c;
        if ((float)inclT > budget && (float)excl <= budget) {   // unique crossing
            s_b0 = ctile*1024 + t;
            s_Sb = excl;
        }
        __syncthreads();
    }

    int b0 = s_b0;
    if (t < 32 && b0 < NBUCK) {
        // extend window bucket-by-bucket until >=8 cost-1 items beyond b0
        int c2cum = 0, pos = b0 + 1, b1 = NBUCK-1; bool done = false;
        while (!done && pos < NBUCK) {
            int idx = pos + lane;
            unsigned long long h = (idx < NBUCK) ? hist[idx] : 0ull;
            int k = (int)((h >> 40) & 0xFFFFFull);
            int inck = k;
            #pragma unroll
            for (int off = 1; off < 32; off <<= 1) {
                int v = __shfl_up_sync(0xffffffffu, inck, off);
                if (lane >= off) inck += v;
            }
            int tot = __shfl_sync(0xffffffffu, inck, 31);
            unsigned m = __ballot_sync(0xffffffffu, c2cum + inck >= 8);
            if (m) { b1 = min(pos + (__ffs(m) - 1), NBUCK-1); done = true; }
            else   { c2cum += tot; pos += 32; }
        }
        if (lane == 0) g_b1[b] = b1;
    }
    if (t == 0) {
        g_b0[b] = b0;
        g_Sbefore[b] = (float)s_Sb;
        if (b0 == NBUCK) g_b1[b] = -1;   // no crossing: accept all valid
    }
}

// ---- phase-1 decisions + gather window items (4 px / thread) ----
__global__ void kGather(float* __restrict__ out_sel) {
    int q = blockIdx.x * blockDim.x + threadIdx.x;   // NP/4 threads
    int p0 = q << 2;
    int b = p0 >> 16;
    uint4 d4 = *(const uint4*)(g_dsc + p0);
    uchar4 gg = *(const uchar4*)(g_g8 + p0);
    int b0 = g_b0[b], b1 = g_b1[b];
    unsigned dsc[4] = {d4.x, d4.y, d4.z, d4.w};
    int gv[4] = {gg.x, gg.y, gg.z, gg.w};
    signed char sm[4]; float so[4];
    #pragma unroll
    for (int k = 0; k < 4; k++) {
        bool valid = dsc[k] < 0x80000000u;
        int bucket = (int)(dsc[k] >> 16);
        bool acc = valid && bucket < b0;
        sm[k] = acc ? (signed char)gv[k] : (signed char)-1;
        so[k] = acc ? (float)gv[k] : -1.0f;
        if (valid && bucket >= b0 && bucket <= b1) {
            int i = atomicAdd(&g_wcount[b], 1);
            if (i < WCAP)
                g_window[b*WCAP + i] = ((unsigned long long)dsc[k] << 24)
                    | ((unsigned long long)((p0 + k) & 0xFFFF) << 8)
                    | (unsigned long long)gv[k];
        }
    }
    *(char4*)(g_selmap + p0) = make_char4(sm[0], sm[1], sm[2], sm[3]);
    *(float4*)(out_sel + p0) = make_float4(so[0], so[1], so[2], so[3]);
}

// ---- exact ranking sort + sequential greedy replay over the window ----
__global__ void kWindow(const void* __restrict__ budget_p, float* __restrict__ out_sel) {
    __shared__ unsigned long long sk[WCAP];
    int b = blockIdx.x, t = threadIdx.x;
    int n = min(g_wcount[b], WCAP);
    for (int i = t; i < n; i += 512) sk[i] = g_window[b*WCAP + i];
    __syncthreads();
    unsigned long long myk[8]; int myr[8]; int cnt = 0;
    for (int i = t; i < n; i += 512) {
        unsigned long long k = sk[i];
        int r = 0;
        for (int j = 0; j < n; j++) r += (sk[j] < k);   // unique keys -> permutation
        myk[cnt] = k; myr[cnt] = r; cnt++;
    }
    __syncthreads();
    for (int q = 0; q < cnt; q++) sk[myr[q]] = myk[q];
    __syncthreads();
    if (t == 0) {
        float budget = load_budget(budget_p) / (float)NB;
        float usage  = g_Sbefore[b];
        for (int i = 0; i < n; i++) {
            if (usage + 1.0f > budget) break;          // nothing else fits
            unsigned long long k = sk[i];
            int g   = (int)(k & 0xFFu);
            int pix = (int)((k >> 8) & 0xFFFFu);
            float c = (float)cost_of(g);
            if (usage + c <= budget) {
                usage += c;
                int p = b * HWPX + pix;
                g_selmap[p] = (signed char)g;
                out_sel[p]  = (float)g;
            }
        }
    }
}

// ---- big HBM-bound masked copy: 16 consecutive px (4x float4) per thread ----
__global__ void kMaskedCopy(const float* __restrict__ collab, float* __restrict__ out) {
    int tid = blockIdx.x * blockDim.x + threadIdx.x;  // NB*NCH*(HWPX/16) threads
    int q   = tid & 4095;              // 16px-group within plane (fastest -> coalesced)
    int row = tid >> 12;               // b*256 + c
    int c   = row & 255;
    int b   = row >> 8;
    int grp = (c < 64) ? 0 : (c < 192) ? 1 : 2;
    unsigned grp4 = 0x01010101u * (unsigned)grp;

    uint4 s = *(const uint4*)(g_selmap + b * HWPX + (q << 4));
    unsigned eq[4] = { __vcmpeq4(s.x, grp4), __vcmpeq4(s.y, grp4),
                       __vcmpeq4(s.z, grp4), __vcmpeq4(s.w, grp4) };

    size_t base = ((size_t)row << 16) + ((size_t)q << 4);
    float4 v[4];
    #pragma unroll
    for (int k = 0; k < 4; k++) {
        v[k] = make_float4(0.f, 0.f, 0.f, 0.f);
        if (eq[k]) {
            float4 w = *(const float4*)(collab + base + 4*k);
            if (eq[k] & 0x000000FFu) v[k].x = w.x;
            if (eq[k] & 0x0000FF00u) v[k].y = w.y;
            if (eq[k] & 0x00FF0000u) v[k].z = w.z;
            if (eq[k] & 0xFF000000u) v[k].w = w.w;
        }
    }
    #pragma unroll
    for (int k = 0; k < 4; k++)
        *(float4*)(out + base + 4*k) = v[k];
}

extern "C" void kernel_launch(void* const* d_in, const int* in_sizes, int n_in,
                              void* d_out, int out_size) {
    const float* collab = (const float*)d_in[0];
    const float* util   = (const float*)d_in[1];
    const void*  budget = d_in[2];
    float* out     = (float*)d_out;
    float* out_sel = out + (size_t)NP * NCH;

    void *p_hist, *p_wc;
    cudaGetSymbolAddress(&p_hist, g_hist);
    cudaGetSymbolAddress(&p_wc,   g_wcount);
    cudaMemsetAsync(p_hist, 0, sizeof(unsigned long long) * NB * NBUCK);
    cudaMemsetAsync(p_wc,   0, sizeof(int) * NB);

    kArgmax<<<NP/256, 256>>>(util);
    kTileSum<<<NB*NTILE, 256>>>();
    kFindWindow<<<NB, 1024>>>(budget);
    kGather<<<NP/4/256, 256>>>(out_sel);
    kWindow<<<NB, 512>>>(budget, out_sel);
    kMaskedCopy<<<NB*NCH*(HWPX/16)/256, 256>>>(collab, out);
}

// round 6
// speedup vs baseline: 1.1069x; 1.1069x over previous
#include <cuda_runtime.h>
#include <cstdint>

#define NB    5
#define HWPX  65536
#define NP    (NB*HWPX)
#define NCH   256
#define NBUCK 32768         // valid dsc < 0x80000000 -> bucket < 32768
#define NTILE 32            // 32 tiles of 1024 buckets per batch
#define WCAP  4096

// ---- static device scratch (allocation-free) ----
__device__ unsigned int       g_dsc[NP];           // descending-order key of best utility
__device__ unsigned char      g_g8[NP];            // argmax group 0/1/2
__device__ signed char        g_selmap[NP];        // accepted group or -1
__device__ unsigned long long g_hist[NB*NBUCK];    // packed: cost | c1<<20 | c2<<40
__device__ unsigned long long g_tile[NB*NTILE];
__device__ unsigned long long g_window[NB*WCAP];
__device__ int                g_wcount[NB];
__device__ int                g_b0[NB], g_b1[NB];
__device__ float              g_Sbefore[NB];

__device__ __forceinline__ float load_budget(const void* ptr) {
    int iv = *(const int*)ptr;                       // int32 or float32 scalar
    if (iv > 0 && iv < 100000000) return (float)iv;
    return __int_as_float(iv);
}
__device__ __forceinline__ int cost_of(int g) { return (g == 0) ? 4 : (g == 1) ? 2 : 1; }

__device__ __forceinline__ void do_pixel(int p, float u0, float u1, float u2,
                                         unsigned* dsc_o, unsigned char* g_o) {
    int g = 0; float bu = u0;
    if (u1 > bu) { bu = u1; g = 1; }   // strict >: first max wins (jnp.argmax)
    if (u2 > bu) { bu = u2; g = 2; }
    bool valid = bu > 0.0f;
    unsigned int x = __float_as_uint(bu);
    unsigned int dsc = ~((x & 0x80000000u) ? ~x : (x | 0x80000000u)); // descending map
    if (!valid) dsc = 0xFFFFFFFFu;
    *dsc_o = dsc; *g_o = (unsigned char)g;
    if (valid) {
        unsigned long long inc = (unsigned long long)cost_of(g)
            | ((unsigned long long)(g == 1) << 20)
            | ((unsigned long long)(g == 2) << 40);
        atomicAdd(&g_hist[(p >> 16) * NBUCK + (dsc >> 16)], inc);
    }
}

// ---- per-pixel argmax + packed histogram, 4 px / thread vectorized ----
__global__ void kArgmax(const float* __restrict__ util) {
    int q  = blockIdx.x * blockDim.x + threadIdx.x;   // NP/4 threads
    int p0 = q << 2;
    const float4* u = (const float4*)(util + 3 * (size_t)p0);
    float4 a = u[0], b = u[1], c = u[2];
    unsigned d4[4]; unsigned char gg[4];
    do_pixel(p0 + 0, a.x, a.y, a.z, &d4[0], &gg[0]);
    do_pixel(p0 + 1, a.w, b.x, b.y, &d4[1], &gg[1]);
    do_pixel(p0 + 2, b.z, b.w, c.x, &d4[2], &gg[2]);
    do_pixel(p0 + 3, c.y, c.z, c.w, &d4[3], &gg[3]);
    *(uint4*)(g_dsc + p0)  = make_uint4(d4[0], d4[1], d4[2], d4[3]);
    *(uchar4*)(g_g8 + p0)  = make_uchar4(gg[0], gg[1], gg[2], gg[3]);
}

// ---- per-tile (1024 buckets) packed sums ----
__global__ void kTileSum() {
    __shared__ unsigned long long sh[256];
    int t = threadIdx.x;
    const unsigned long long* src = g_hist + (size_t)blockIdx.x * 1024;
    sh[t] = src[t] + src[t+256] + src[t+512] + src[t+768];
    __syncthreads();
    for (int off = 128; off > 0; off >>= 1) {
        if (t < off) sh[t] += sh[t + off];
        __syncthreads();
    }
    if (t == 0) g_tile[blockIdx.x] = sh[0];
}

// ---- one block (1024 thr) per batch: crossing bucket b0 + window end b1 ----
__global__ void kFindWindow(const void* __restrict__ budget_p) {
    __shared__ unsigned s_tile[NTILE];
    __shared__ unsigned s_wsum[32];
    __shared__ int s_ctile, s_b0;
    __shared__ unsigned s_cumbase, s_Sb;

    int b = blockIdx.x, t = threadIdx.x;
    int wid = t >> 5, lane = t & 31;
    float budget = load_budget(budget_p) / (float)NB;
    const unsigned long long* hist = g_hist + (size_t)b * NBUCK;

    if (t < NTILE) s_tile[t] = (unsigned)(g_tile[b*NTILE + t] & 0xFFFFFu);
    if (t == 0) { s_ctile = -1; s_cumbase = 0; s_b0 = NBUCK; s_Sb = 0; }
    __syncthreads();

    if (t == 0) {   // tile-level crossing
        unsigned cum = 0;
        for (int q = 0; q < NTILE; q++) {
            unsigned c = s_tile[q];
            if ((float)(cum + c) > budget) { s_ctile = q; s_cumbase = cum; break; }
            cum += c;
        }
    }
    __syncthreads();
    int ctile = s_ctile;

    if (ctile >= 0) {   // in-tile block scan over 1024 buckets
        unsigned c = (unsigned)(hist[ctile*1024 + t] & 0xFFFFFu);
        unsigned inc = c;
        #pragma unroll
        for (int off = 1; off < 32; off <<= 1) {
            unsigned v = __shfl_up_sync(0xffffffffu, inc, off);
            if (lane >= off) inc += v;
        }
        if (lane == 31) s_wsum[wid] = inc;
        __syncthreads();
        if (wid == 0) {
            unsigned w = s_wsum[lane];
            #pragma unroll
            for (int off = 1; off < 32; off <<= 1) {
                unsigned v = __shfl_up_sync(0xffffffffu, w, off);
                if (lane >= off) w += v;
            }
            s_wsum[lane] = w;
        }
        __syncthreads();
        unsigned woff = (wid > 0) ? s_wsum[wid-1] : 0u;
        unsigned inclT = s_cumbase + woff + inc;
        unsigned excl  = inclT - c;
        if ((float)inclT > budget && (float)excl <= budget) {   // unique crossing
            s_b0 = ctile*1024 + t;
            s_Sb = excl;
        }
        __syncthreads();
    }

    int b0 = s_b0;
    if (t < 32 && b0 < NBUCK) {
        // extend window bucket-by-bucket until >=8 cost-1 items beyond b0
        int c2cum = 0, pos = b0 + 1, b1 = NBUCK-1; bool done = false;
        while (!done && pos < NBUCK) {
            int idx = pos + lane;
            unsigned long long h = (idx < NBUCK) ? hist[idx] : 0ull;
            int k = (int)((h >> 40) & 0xFFFFFull);
            int inck = k;
            #pragma unroll
            for (int off = 1; off < 32; off <<= 1) {
                int v = __shfl_up_sync(0xffffffffu, inck, off);
                if (lane >= off) inck += v;
            }
            int tot = __shfl_sync(0xffffffffu, inck, 31);
            unsigned m = __ballot_sync(0xffffffffu, c2cum + inck >= 8);
            if (m) { b1 = min(pos + (__ffs(m) - 1), NBUCK-1); done = true; }
            else   { c2cum += tot; pos += 32; }
        }
        if (lane == 0) g_b1[b] = b1;
    }
    if (t == 0) {
        g_b0[b] = b0;
        g_Sbefore[b] = (float)s_Sb;
        if (b0 == NBUCK) g_b1[b] = -1;   // no crossing: accept all valid
    }
}

// ---- phase-1 decisions + gather window items (4 px / thread) ----
__global__ void kGather(float* __restrict__ out_sel) {
    int q = blockIdx.x * blockDim.x + threadIdx.x;   // NP/4 threads
    int p0 = q << 2;
    int b = p0 >> 16;
    uint4 d4 = *(const uint4*)(g_dsc + p0);
    uchar4 gg = *(const uchar4*)(g_g8 + p0);
    int b0 = g_b0[b], b1 = g_b1[b];
    unsigned dsc[4] = {d4.x, d4.y, d4.z, d4.w};
    int gv[4] = {gg.x, gg.y, gg.z, gg.w};
    signed char sm[4]; float so[4];
    #pragma unroll
    for (int k = 0; k < 4; k++) {
        bool valid = dsc[k] < 0x80000000u;
        int bucket = (int)(dsc[k] >> 16);
        bool acc = valid && bucket < b0;
        sm[k] = acc ? (signed char)gv[k] : (signed char)-1;
        so[k] = acc ? (float)gv[k] : -1.0f;
        if (valid && bucket >= b0 && bucket <= b1) {
            int i = atomicAdd(&g_wcount[b], 1);
            if (i < WCAP)
                g_window[b*WCAP + i] = ((unsigned long long)dsc[k] << 24)
                    | ((unsigned long long)((p0 + k) & 0xFFFF) << 8)
                    | (unsigned long long)gv[k];
        }
    }
    *(char4*)(g_selmap + p0) = make_char4(sm[0], sm[1], sm[2], sm[3]);
    *(float4*)(out_sel + p0) = make_float4(so[0], so[1], so[2], so[3]);
}

// ---- exact ranking sort + sequential greedy replay over the window ----
__global__ void kWindow(const void* __restrict__ budget_p, float* __restrict__ out_sel) {
    __shared__ unsigned long long sk[WCAP];
    int b = blockIdx.x, t = threadIdx.x;
    int n = min(g_wcount[b], WCAP);
    for (int i = t; i < n; i += 512) sk[i] = g_window[b*WCAP + i];
    __syncthreads();
    unsigned long long myk[8]; int myr[8]; int cnt = 0;
    for (int i = t; i < n; i += 512) {
        unsigned long long k = sk[i];
        int r = 0;
        for (int j = 0; j < n; j++) r += (sk[j] < k);   // unique keys -> permutation
        myk[cnt] = k; myr[cnt] = r; cnt++;
    }
    __syncthreads();
    for (int q = 0; q < cnt; q++) sk[myr[q]] = myk[q];
    __syncthreads();
    if (t == 0) {
        float budget = load_budget(budget_p) / (float)NB;
        float usage  = g_Sbefore[b];
        for (int i = 0; i < n; i++) {
            if (usage + 1.0f > budget) break;          // nothing else fits
            unsigned long long k = sk[i];
            int g   = (int)(k & 0xFFu);
            int pix = (int)((k >> 8) & 0xFFFFu);
            float c = (float)cost_of(g);
            if (usage + c <= budget) {
                usage += c;
                int p = b * HWPX + pix;
                g_selmap[p] = (signed char)g;
                out_sel[p]  = (float)g;
            }
        }
    }
}

// ---- big HBM-bound masked copy: R3 structure (1 thread = 1 float4) + streaming hints ----
__global__ void kMaskedCopy(const float* __restrict__ collab, float* __restrict__ out) {
    int tid = blockIdx.x * blockDim.x + threadIdx.x;  // (NP/4)*NCH/256 blocks
    int row = tid >> 14;               // b*256 + c
    int o   = (tid & 16383) << 2;      // hw offset, multiple of 4
    int c   = row & 255;
    int b   = row >> 8;
    int grp = (c < 64) ? 0 : (c < 192) ? 1 : 2;
    char4 s4 = *(const char4*)(g_selmap + b * HWPX + o);
    bool m0 = (s4.x == grp), m1 = (s4.y == grp), m2 = (s4.z == grp), m3 = (s4.w == grp);
    float4 v = make_float4(0.f, 0.f, 0.f, 0.f);
    size_t idx = ((size_t)row << 16) + (size_t)o;
    if (m0 | m1 | m2 | m3) {
        v = __ldcs((const float4*)(collab + idx));   // streaming read (read-once)
        if (!m0) v.x = 0.f;
        if (!m1) v.y = 0.f;
        if (!m2) v.z = 0.f;
        if (!m3) v.w = 0.f;
    }
    __stcs((float4*)(out + idx), v);                 // streaming write (write-once)
}

extern "C" void kernel_launch(void* const* d_in, const int* in_sizes, int n_in,
                              void* d_out, int out_size) {
    const float* collab = (const float*)d_in[0];
    const float* util   = (const float*)d_in[1];
    const void*  budget = d_in[2];
    float* out     = (float*)d_out;
    float* out_sel = out + (size_t)NP * NCH;

    void *p_hist, *p_wc;
    cudaGetSymbolAddress(&p_hist, g_hist);
    cudaGetSymbolAddress(&p_wc,   g_wcount);
    cudaMemsetAsync(p_hist, 0, sizeof(unsigned long long) * NB * NBUCK);
    cudaMemsetAsync(p_wc,   0, sizeof(int) * NB);

    kArgmax<<<NP/4/256, 256>>>(util);
    kTileSum<<<NB*NTILE, 256>>>();
    kFindWindow<<<NB, 1024>>>(budget);
    kGather<<<NP/4/256, 256>>>(out_sel);
    kWindow<<<NB, 512>>>(budget, out_sel);
    kMaskedCopy<<<(NP/4)*NCH/256, 256>>>(collab, out);
}